// round 12
// baseline (speedup 1.0000x reference)
#include <cuda_runtime.h>
#include <cstdint>
#include <math.h>
#include <math_constants.h>

#define Bb   8
#define Sx   1024
#define Hh   16
#define Dd   64
#define HIDD 1024

__device__ float g_q[Bb * Hh * Sx * Dd];
__device__ float g_k[Bb * Hh * Sx * Dd];
__device__ float g_wt[2][HIDD * HIDD];

typedef unsigned long long u64;

// ---------------------------------------------------------------------------
// Packed fp32x2 helpers (attention kernel)
// ---------------------------------------------------------------------------
__device__ __forceinline__ u64 pk(float lo, float hi) {
    u64 r;
    asm("mov.b64 %0, {%1, %2};"
        : "=l"(r) : "r"(__float_as_uint(lo)), "r"(__float_as_uint(hi)));
    return r;
}
__device__ __forceinline__ void upk(u64 v, float& lo, float& hi) {
    unsigned int a, b;
    asm("mov.b64 {%0, %1}, %2;" : "=r"(a), "=r"(b) : "l"(v));
    lo = __uint_as_float(a);
    hi = __uint_as_float(b);
}
__device__ __forceinline__ void fma2(u64& d, u64 a, u64 b) {
    asm("fma.rn.f32x2 %0, %1, %2, %0;" : "+l"(d) : "l"(a), "l"(b));
}
__device__ __forceinline__ u64 mul2(u64 a, u64 b) {
    u64 r;
    asm("mul.rn.f32x2 %0, %1, %2;" : "=l"(r) : "l"(a), "l"(b));
    return r;
}

// ---------------------------------------------------------------------------
// bf16 helpers (mma.sync m16n8k16 — plain sm_80+ PTX)
// ---------------------------------------------------------------------------
__device__ __forceinline__ uint32_t cvt_bf16x2(float lo, float hi) {
    // result = {hi16: cvt(hi), lo16: cvt(lo)}
    uint32_t r;
    asm("cvt.rn.bf16x2.f32 %0, %1, %2;" : "=r"(r) : "f"(hi), "f"(lo));
    return r;
}
__device__ __forceinline__ void mma_bf16(float c[4],
    uint32_t a0, uint32_t a1, uint32_t a2, uint32_t a3,
    uint32_t b0, uint32_t b1)
{
    asm volatile(
        "mma.sync.aligned.m16n8k16.row.col.f32.bf16.bf16.f32 "
        "{%0,%1,%2,%3}, {%4,%5,%6,%7}, {%8,%9}, {%0,%1,%2,%3};"
        : "+f"(c[0]), "+f"(c[1]), "+f"(c[2]), "+f"(c[3])
        : "r"(a0), "r"(a1), "r"(a2), "r"(a3), "r"(b0), "r"(b1));
}

// ---------------------------------------------------------------------------
// Weight transpose: g_wt[z][n][k] = W[k][n]   (measured ~6 us)
// ---------------------------------------------------------------------------
__global__ __launch_bounds__(256) void transpose_w(
    const float* __restrict__ Wq, const float* __restrict__ Wk)
{
    __shared__ float t[32][33];
    const float* W = (blockIdx.z == 0) ? Wq : Wk;
    float* dst = g_wt[blockIdx.z];
    const int x0 = blockIdx.x * 32, y0 = blockIdx.y * 32;
    const int tx = threadIdx.x & 31, ty = threadIdx.x >> 5;
    #pragma unroll
    for (int r = ty; r < 32; r += 8)
        t[r][tx] = W[(size_t)(y0 + r) * HIDD + x0 + tx];
    __syncthreads();
    #pragma unroll
    for (int r = ty; r < 32; r += 8)
        dst[(size_t)(x0 + r) * HIDD + y0 + tx] = t[tx][r];
}

// ---------------------------------------------------------------------------
// Projection GEMM: mma.sync bf16 m16n8k16, 3-term split
//   D = Ah@Bh + Ah@Bl + Al@Bh,   x = bf16_hi(x) + bf16_lo(x - hi)
// 128x128 tile, 8 warps = 4(m) x 2(n), warp tile 32x64.
// K chunked by 16 (one k16 mma per fragment set). Pair-packed smem, pitch 12.
// ---------------------------------------------------------------------------
#define KC      16
#define PITCHP  12   // pairs per row incl. pad (8 data + 4); 12g+qd distinct mod 32

__global__ __launch_bounds__(256, 2) void proj_mma_kernel(
    const float* __restrict__ X,
    const float* __restrict__ bq, const float* __restrict__ bk)
{
    __shared__ uint32_t Ah[128 * PITCHP], Al[128 * PITCHP];
    __shared__ uint32_t Bh[128 * PITCHP], Bl[128 * PITCHP];

    const int tid = threadIdx.x;
    const int wid = tid >> 5, lane = tid & 31;
    const int grp = lane >> 2, qd = lane & 3;
    const int z = blockIdx.z;
    const int n0 = blockIdx.x * 128, m0 = blockIdx.y * 128;
    const float* Wt = g_wt[z];
    const float* bias = z ? bk : bq;
    float* dst = z ? g_k : g_q;

    const int mrow = (wid & 3) * 32;
    const int ncol = (wid >> 2) * 64;

    float acc[2][8][4];
    #pragma unroll
    for (int mf = 0; mf < 2; mf++)
        #pragma unroll
        for (int nf = 0; nf < 8; nf++)
            #pragma unroll
            for (int r = 0; r < 4; r++) acc[mf][nf][r] = 0.f;

    for (int c = 0; c < HIDD / KC; c++) {
        const int kbase = c * KC;
        __syncthreads();
        // Stage A (hidden) and B (Wt) chunks, split to bf16 hi/lo pair-packed.
        #pragma unroll
        for (int half = 0; half < 2; half++) {
            const float* src = half ? (Wt + (size_t)n0 * HIDD + kbase)
                                    : (X + (size_t)m0 * HIDD + kbase);
            uint32_t* dh = half ? Bh : Ah;
            uint32_t* dl = half ? Bl : Al;
            #pragma unroll
            for (int i = tid; i < 512; i += 256) {
                int row = i >> 2, s = i & 3;  // s: which float4 (4 k = 2 pairs)
                float4 v = *reinterpret_cast<const float4*>(
                    src + (size_t)row * HIDD + s * 4);
                uint32_t h0 = cvt_bf16x2(v.x, v.y);
                float hx = __uint_as_float(h0 << 16);
                float hy = __uint_as_float(h0 & 0xffff0000u);
                uint32_t l0 = cvt_bf16x2(v.x - hx, v.y - hy);
                uint32_t h1 = cvt_bf16x2(v.z, v.w);
                float hz = __uint_as_float(h1 << 16);
                float hw = __uint_as_float(h1 & 0xffff0000u);
                uint32_t l1 = cvt_bf16x2(v.z - hz, v.w - hw);
                int o = row * PITCHP + 2 * s;
                dh[o] = h0; dh[o + 1] = h1;
                dl[o] = l0; dl[o + 1] = l1;
            }
        }
        __syncthreads();

        // Fragments: A pairs [row][qd], [row][qd+4]; B pairs [n][qd], [n][qd+4]
        uint32_t ah[2][4], al[2][4];
        #pragma unroll
        for (int mf = 0; mf < 2; mf++) {
            int r0 = (mrow + mf * 16 + grp) * PITCHP + qd;
            int r1 = (mrow + mf * 16 + grp + 8) * PITCHP + qd;
            ah[mf][0] = Ah[r0];     ah[mf][1] = Ah[r1];
            ah[mf][2] = Ah[r0 + 4]; ah[mf][3] = Ah[r1 + 4];
            al[mf][0] = Al[r0];     al[mf][1] = Al[r1];
            al[mf][2] = Al[r0 + 4]; al[mf][3] = Al[r1 + 4];
        }
        #pragma unroll
        for (int nf = 0; nf < 8; nf++) {
            int bb = (ncol + nf * 8 + grp) * PITCHP + qd;
            uint32_t bh0 = Bh[bb], bh1 = Bh[bb + 4];
            uint32_t bl0 = Bl[bb], bl1 = Bl[bb + 4];
            #pragma unroll
            for (int mf = 0; mf < 2; mf++) {
                mma_bf16(acc[mf][nf], ah[mf][0], ah[mf][1], ah[mf][2], ah[mf][3], bh0, bh1);
                mma_bf16(acc[mf][nf], ah[mf][0], ah[mf][1], ah[mf][2], ah[mf][3], bl0, bl1);
                mma_bf16(acc[mf][nf], al[mf][0], al[mf][1], al[mf][2], al[mf][3], bh0, bh1);
            }
        }
    }

    #pragma unroll
    for (int mf = 0; mf < 2; mf++) {
        #pragma unroll
        for (int rr = 0; rr < 2; rr++) {
            int m = m0 + mrow + mf * 16 + grp + rr * 8;
            int bidx = m >> 10, s = m & 1023;
            size_t rowbase = ((size_t)bidx * Hh) * Sx;
            #pragma unroll
            for (int nf = 0; nf < 8; nf++) {
                int n = n0 + ncol + nf * 8 + qd * 2;
                int h = n >> 6, d = n & 63;
                float2 o;
                o.x = acc[mf][nf][rr * 2 + 0] + bias[n];
                o.y = acc[mf][nf][rr * 2 + 1] + bias[n + 1];
                *reinterpret_cast<float2*>(
                    &dst[((rowbase + (size_t)h * Sx + s)) * Dd + d]) = o;
            }
        }
    }
}

// ---------------------------------------------------------------------------
// Fused attention — EXACT round-2 kernel (measured 1751 us). Do not touch.
// ---------------------------------------------------------------------------
#define PQ  68
#define PK  66
#define PKS 68
#define PT  130
#define PP  66

#define ATT_SMEM_FLOATS (64 * (PQ + PK + PKS + PT + PP))
#define ATT_SMEM_BYTES  (ATT_SMEM_FLOATS * 4)

__global__ __launch_bounds__(256, 2) void attn_kernel(
    const float* __restrict__ dist, float* __restrict__ out)
{
    extern __shared__ float sm[];
    float* q_t = sm;
    float* k_t = q_t + 64 * PQ;
    float* k_s = k_t + 64 * PK;
    float* T_t = k_s + 64 * PKS;
    float* p_s = T_t + 64 * PT;

    const int tid = threadIdx.x;
    const int tx = tid & 15, ty = tid >> 4;
    const int bh = blockIdx.y;
    const int b = bh >> 4, h = bh & 15;
    const int l0 = blockIdx.x * 64;

    const float* qg = g_q + (size_t)bh * Sx * Dd;
    const float* kg = g_k + (size_t)bh * Sx * Dd;

    for (int idx = tid; idx < 64 * 16; idx += 256) {
        int l = idx >> 4, d4 = (idx & 15) * 4;
        float4 v = *reinterpret_cast<const float4*>(qg + (size_t)(l0 + l) * 64 + d4);
        q_t[(d4 + 0) * PQ + l] = v.x;
        q_t[(d4 + 1) * PQ + l] = v.y;
        q_t[(d4 + 2) * PQ + l] = v.z;
        q_t[(d4 + 3) * PQ + l] = v.w;
    }

    float mrow[4], lrow[4];
    u64 o_p[4][2];
    #pragma unroll
    for (int ii = 0; ii < 4; ii++) {
        mrow[ii] = -CUDART_INF_F;
        lrow[ii] = 0.f;
        o_p[ii][0] = 0ULL;
        o_p[ii][1] = 0ULL;
    }

    const int base = (ty - tx) * 4 + 63;

    for (int r0 = 0; r0 < Sx; r0 += 64) {
        __syncthreads();
        for (int idx = tid; idx < 64 * 16; idx += 256) {
            int r = idx >> 4, d4 = (idx & 15) * 4;
            float4 v = *reinterpret_cast<const float4*>(kg + (size_t)(r0 + r) * 64 + d4);
            *reinterpret_cast<float4*>(&k_s[r * PKS + d4]) = v;
            k_t[(d4 + 0) * PK + r] = v.x;
            k_t[(d4 + 1) * PK + r] = v.y;
            k_t[(d4 + 2) * PK + r] = v.z;
            k_t[(d4 + 3) * PK + r] = v.w;
        }
        const int off = l0 - r0 + 960;
        for (int idx = tid; idx < 127 * 16; idx += 256) {
            int row = idx >> 4, d4 = (idx & 15) * 4;
            float4 v = *reinterpret_cast<const float4*>(dist + (size_t)(off + row) * 64 + d4);
            T_t[(d4 + 0) * PT + row] = v.x;
            T_t[(d4 + 1) * PT + row] = v.y;
            T_t[(d4 + 2) * PT + row] = v.z;
            T_t[(d4 + 3) * PT + row] = v.w;
        }
        __syncthreads();

        u64 accs_p[4][2], accq_p[4][2], acck_p[2][4];
        #pragma unroll
        for (int i = 0; i < 4; i++) {
            accs_p[i][0] = 0ULL; accs_p[i][1] = 0ULL;
            accq_p[i][0] = 0ULL; accq_p[i][1] = 0ULL;
        }
        #pragma unroll
        for (int i = 0; i < 2; i++)
            #pragma unroll
            for (int j = 0; j < 4; j++) acck_p[i][j] = 0ULL;

        for (int d = 0; d < 64; d++) {
            float4 qv = *reinterpret_cast<float4*>(&q_t[d * PQ + ty * 4]);
            u64 qd[4];
            qd[0] = pk(qv.x, qv.x); qd[1] = pk(qv.y, qv.y);
            qd[2] = pk(qv.z, qv.z); qd[3] = pk(qv.w, qv.w);

            float2 kc0 = *reinterpret_cast<float2*>(&k_t[d * PK + tx * 4]);
            float2 kc1 = *reinterpret_cast<float2*>(&k_t[d * PK + tx * 4 + 2]);
            u64 kp[2];
            kp[0] = pk(kc0.x, kc0.y);
            kp[1] = pk(kc1.x, kc1.y);
            u64 kd[4];
            kd[0] = pk(kc0.x, kc0.x); kd[1] = pk(kc0.y, kc0.y);
            kd[2] = pk(kc1.x, kc1.x); kd[3] = pk(kc1.y, kc1.y);

            const float* Trow = &T_t[d * PT + base - 3];
            float2 e0 = *reinterpret_cast<const float2*>(Trow);
            float2 e1 = *reinterpret_cast<const float2*>(Trow + 2);
            float2 e2 = *reinterpret_cast<const float2*>(Trow + 4);
            float  s3 = Trow[6];
            u64 tp[6];
            tp[0] = pk(e0.x, e0.y);
            tp[1] = pk(e0.y, e1.x);
            tp[2] = pk(e1.x, e1.y);
            tp[3] = pk(e1.y, e2.x);
            tp[4] = pk(e2.x, e2.y);
            tp[5] = pk(e2.y, s3);

            #pragma unroll
            for (int ii = 0; ii < 4; ii++)
                #pragma unroll
                for (int jp = 0; jp < 2; jp++) {
                    fma2(accs_p[ii][jp], qd[ii], kp[jp]);
                    fma2(accq_p[ii][jp], qd[ii], tp[ii - 2 * jp + 2]);
                }
            #pragma unroll
            for (int ip = 0; ip < 2; ip++)
                #pragma unroll
                for (int jj = 0; jj < 4; jj++)
                    fma2(acck_p[ip][jj], kd[jj], tp[2 * ip - jj + 3]);
        }

        float st[4][4];
        #pragma unroll
        for (int ii = 0; ii < 4; ii++)
            #pragma unroll
            for (int jp = 0; jp < 2; jp++) {
                float a0, a1;
                upk(accs_p[ii][jp], a0, a1);
                st[ii][2 * jp] = a0;
                st[ii][2 * jp + 1] = a1;
                upk(accq_p[ii][jp], a0, a1);
                st[ii][2 * jp + 1] += a0;
                st[ii][2 * jp] += a1;
            }
        #pragma unroll
        for (int ip = 0; ip < 2; ip++)
            #pragma unroll
            for (int jj = 0; jj < 4; jj++) {
                float a0, a1;
                upk(acck_p[ip][jj], a0, a1);
                st[2 * ip][jj] += a0;
                st[2 * ip + 1][jj] += a1;
            }

        #pragma unroll
        for (int ii = 0; ii < 4; ii++) {
            float tmax = -CUDART_INF_F;
            #pragma unroll
            for (int jj = 0; jj < 4; jj++) {
                st[ii][jj] *= 0.125f;
                tmax = fmaxf(tmax, st[ii][jj]);
            }
            #pragma unroll
            for (int ofs = 8; ofs >= 1; ofs >>= 1)
                tmax = fmaxf(tmax, __shfl_xor_sync(0xffffffffu, tmax, ofs));
            float mnew = fmaxf(mrow[ii], tmax);
            float corr = __expf(mrow[ii] - mnew);
            mrow[ii] = mnew;
            float psum = 0.f;
            #pragma unroll
            for (int jj = 0; jj < 4; jj++) {
                float p = __expf(st[ii][jj] - mnew);
                st[ii][jj] = p;
                psum += p;
            }
            #pragma unroll
            for (int ofs = 8; ofs >= 1; ofs >>= 1)
                psum += __shfl_xor_sync(0xffffffffu, psum, ofs);
            lrow[ii] = lrow[ii] * corr + psum;
            u64 c2 = pk(corr, corr);
            o_p[ii][0] = mul2(o_p[ii][0], c2);
            o_p[ii][1] = mul2(o_p[ii][1], c2);
        }

        #pragma unroll
        for (int ii = 0; ii < 4; ii++)
            #pragma unroll
            for (int jj = 0; jj < 4; jj++)
                p_s[(ty * 4 + ii) * PP + tx * 4 + jj] = st[ii][jj];
        __syncthreads();

        for (int j = 0; j < 64; j += 2) {
            float4 va4 = *reinterpret_cast<float4*>(&k_s[j * PKS + tx * 4]);
            float4 vb4 = *reinterpret_cast<float4*>(&k_s[(j + 1) * PKS + tx * 4]);
            u64 va0 = pk(va4.x, va4.y), va1 = pk(va4.z, va4.w);
            u64 vb0 = pk(vb4.x, vb4.y), vb1 = pk(vb4.z, vb4.w);
            #pragma unroll
            for (int ii = 0; ii < 4; ii++) {
                float2 p2 = *reinterpret_cast<float2*>(&p_s[(ty * 4 + ii) * PP + j]);
                u64 pa = pk(p2.x, p2.x);
                u64 pb = pk(p2.y, p2.y);
                fma2(o_p[ii][0], pa, va0);
                fma2(o_p[ii][1], pa, va1);
                fma2(o_p[ii][0], pb, vb0);
                fma2(o_p[ii][1], pb, vb1);
            }
        }
    }

    #pragma unroll
    for (int ii = 0; ii < 4; ii++) {
        float inv = 1.0f / lrow[ii];
        int srow = l0 + ty * 4 + ii;
        size_t obase = ((size_t)b * Sx + srow) * HIDD + h * 64 + tx * 4;
        float o0, o1, o2, o3;
        upk(o_p[ii][0], o0, o1);
        upk(o_p[ii][1], o2, o3);
        float4 ov;
        ov.x = o0 * inv; ov.y = o1 * inv; ov.z = o2 * inv; ov.w = o3 * inv;
        *reinterpret_cast<float4*>(&out[obase]) = ov;
    }
}

// ---------------------------------------------------------------------------
extern "C" void kernel_launch(void* const* d_in, const int* in_sizes, int n_in,
                              void* d_out, int out_size)
{
    const float* hidden = (const float*)d_in[0];
    const float* Wq = (const float*)d_in[1];
    const float* bq = (const float*)d_in[2];
    const float* Wk = (const float*)d_in[3];
    const float* bk = (const float*)d_in[4];
    // d_in[5], d_in[6] (Wv, bv) dead: reference uses k-projection as v.
    const float* dist = (const float*)d_in[7];
    float* out = (float*)d_out;

    cudaFuncSetAttribute(attn_kernel,
                         cudaFuncAttributeMaxDynamicSharedMemorySize,
                         ATT_SMEM_BYTES);

    transpose_w<<<dim3(32, 32, 2), 256>>>(Wq, Wk);
    proj_mma_kernel<<<dim3(HIDD / 128, (Bb * Sx) / 128, 2), 256>>>(
        hidden, bq, bk);
    attn_kernel<<<dim3(Sx / 64, Bb * Hh), 256, ATT_SMEM_BYTES>>>(dist, out);
}

// round 13
// speedup vs baseline: 1.0460x; 1.0460x over previous
#include <cuda_runtime.h>
#include <cstdint>
#include <math.h>
#include <math_constants.h>

#define Bb   8
#define Sx   1024
#define Hh   16
#define Dd   64
#define HIDD 1024

__device__ float g_q[Bb * Hh * Sx * Dd];
__device__ float g_k[Bb * Hh * Sx * Dd];
__device__ float g_wt[2][HIDD * HIDD];

typedef unsigned long long u64;

// ---------------------------------------------------------------------------
// Packed fp32x2 helpers (attention kernel)
// ---------------------------------------------------------------------------
__device__ __forceinline__ u64 pk(float lo, float hi) {
    u64 r;
    asm("mov.b64 %0, {%1, %2};"
        : "=l"(r) : "r"(__float_as_uint(lo)), "r"(__float_as_uint(hi)));
    return r;
}
__device__ __forceinline__ void upk(u64 v, float& lo, float& hi) {
    unsigned int a, b;
    asm("mov.b64 {%0, %1}, %2;" : "=r"(a), "=r"(b) : "l"(v));
    lo = __uint_as_float(a);
    hi = __uint_as_float(b);
}
__device__ __forceinline__ void fma2(u64& d, u64 a, u64 b) {
    asm("fma.rn.f32x2 %0, %1, %2, %0;" : "+l"(d) : "l"(a), "l"(b));
}
__device__ __forceinline__ u64 mul2(u64 a, u64 b) {
    u64 r;
    asm("mul.rn.f32x2 %0, %1, %2;" : "=l"(r) : "l"(a), "l"(b));
    return r;
}

// ---------------------------------------------------------------------------
// bf16 helpers (mma.sync m16n8k16 — plain sm_80+ PTX)
// ---------------------------------------------------------------------------
__device__ __forceinline__ uint32_t cvt_bf16x2(float lo, float hi) {
    // result = {hi16: cvt(hi), lo16: cvt(lo)}
    uint32_t r;
    asm("cvt.rn.bf16x2.f32 %0, %1, %2;" : "=r"(r) : "f"(hi), "f"(lo));
    return r;
}
__device__ __forceinline__ void mma_bf16(float c[4],
    uint32_t a0, uint32_t a1, uint32_t a2, uint32_t a3,
    uint32_t b0, uint32_t b1)
{
    asm volatile(
        "mma.sync.aligned.m16n8k16.row.col.f32.bf16.bf16.f32 "
        "{%0,%1,%2,%3}, {%4,%5,%6,%7}, {%8,%9}, {%0,%1,%2,%3};"
        : "+f"(c[0]), "+f"(c[1]), "+f"(c[2]), "+f"(c[3])
        : "r"(a0), "r"(a1), "r"(a2), "r"(a3), "r"(b0), "r"(b1));
}

// ---------------------------------------------------------------------------
// Weight transpose: g_wt[z][n][k] = W[k][n]   (measured ~6 us)
// ---------------------------------------------------------------------------
__global__ __launch_bounds__(256) void transpose_w(
    const float* __restrict__ Wq, const float* __restrict__ Wk)
{
    __shared__ float t[32][33];
    const float* W = (blockIdx.z == 0) ? Wq : Wk;
    float* dst = g_wt[blockIdx.z];
    const int x0 = blockIdx.x * 32, y0 = blockIdx.y * 32;
    const int tx = threadIdx.x & 31, ty = threadIdx.x >> 5;
    #pragma unroll
    for (int r = ty; r < 32; r += 8)
        t[r][tx] = W[(size_t)(y0 + r) * HIDD + x0 + tx];
    __syncthreads();
    #pragma unroll
    for (int r = ty; r < 32; r += 8)
        dst[(size_t)(x0 + r) * HIDD + y0 + tx] = t[tx][r];
}

// ---------------------------------------------------------------------------
// Projection GEMM: mma.sync bf16 m16n8k16, 3-term split
//   D = Ah@Bh + Ah@Bl + Al@Bh,   x = bf16_hi(x) + bf16_lo(x - hi)
// 128x128 tile, 8 warps = 4(m) x 2(n), warp tile 32x64.
// K chunked by 16 (one k16 mma per fragment set). Pair-packed smem, pitch 12.
// ---------------------------------------------------------------------------
#define KC      16
#define PITCHP  12   // pairs per row incl. pad (8 data + 4); 12g+qd distinct mod 32

__global__ __launch_bounds__(256, 2) void proj_mma_kernel(
    const float* __restrict__ X,
    const float* __restrict__ bq, const float* __restrict__ bk)
{
    __shared__ uint32_t Ah[128 * PITCHP], Al[128 * PITCHP];
    __shared__ uint32_t Bh[128 * PITCHP], Bl[128 * PITCHP];

    const int tid = threadIdx.x;
    const int wid = tid >> 5, lane = tid & 31;
    const int grp = lane >> 2, qd = lane & 3;
    const int z = blockIdx.z;
    const int n0 = blockIdx.x * 128, m0 = blockIdx.y * 128;
    const float* Wt = g_wt[z];
    const float* bias = z ? bk : bq;
    float* dst = z ? g_k : g_q;

    const int mrow = (wid & 3) * 32;
    const int ncol = (wid >> 2) * 64;

    float acc[2][8][4];
    #pragma unroll
    for (int mf = 0; mf < 2; mf++)
        #pragma unroll
        for (int nf = 0; nf < 8; nf++)
            #pragma unroll
            for (int r = 0; r < 4; r++) acc[mf][nf][r] = 0.f;

    for (int c = 0; c < HIDD / KC; c++) {
        const int kbase = c * KC;
        __syncthreads();
        // Stage A (hidden) and B (Wt) chunks, split to bf16 hi/lo pair-packed.
        #pragma unroll
        for (int half = 0; half < 2; half++) {
            const float* src = half ? (Wt + (size_t)n0 * HIDD + kbase)
                                    : (X + (size_t)m0 * HIDD + kbase);
            uint32_t* dh = half ? Bh : Ah;
            uint32_t* dl = half ? Bl : Al;
            #pragma unroll
            for (int i = tid; i < 512; i += 256) {
                int row = i >> 2, s = i & 3;  // s: which float4 (4 k = 2 pairs)
                float4 v = *reinterpret_cast<const float4*>(
                    src + (size_t)row * HIDD + s * 4);
                uint32_t h0 = cvt_bf16x2(v.x, v.y);
                float hx = __uint_as_float(h0 << 16);
                float hy = __uint_as_float(h0 & 0xffff0000u);
                uint32_t l0 = cvt_bf16x2(v.x - hx, v.y - hy);
                uint32_t h1 = cvt_bf16x2(v.z, v.w);
                float hz = __uint_as_float(h1 << 16);
                float hw = __uint_as_float(h1 & 0xffff0000u);
                uint32_t l1 = cvt_bf16x2(v.z - hz, v.w - hw);
                int o = row * PITCHP + 2 * s;
                dh[o] = h0; dh[o + 1] = h1;
                dl[o] = l0; dl[o + 1] = l1;
            }
        }
        __syncthreads();

        // Fragments: A pairs [row][qd], [row][qd+4]; B pairs [n][qd], [n][qd+4]
        uint32_t ah[2][4], al[2][4];
        #pragma unroll
        for (int mf = 0; mf < 2; mf++) {
            int r0 = (mrow + mf * 16 + grp) * PITCHP + qd;
            int r1 = (mrow + mf * 16 + grp + 8) * PITCHP + qd;
            ah[mf][0] = Ah[r0];     ah[mf][1] = Ah[r1];
            ah[mf][2] = Ah[r0 + 4]; ah[mf][3] = Ah[r1 + 4];
            al[mf][0] = Al[r0];     al[mf][1] = Al[r1];
            al[mf][2] = Al[r0 + 4]; al[mf][3] = Al[r1 + 4];
        }
        #pragma unroll
        for (int nf = 0; nf < 8; nf++) {
            int bb = (ncol + nf * 8 + grp) * PITCHP + qd;
            uint32_t bh0 = Bh[bb], bh1 = Bh[bb + 4];
            uint32_t bl0 = Bl[bb], bl1 = Bl[bb + 4];
            #pragma unroll
            for (int mf = 0; mf < 2; mf++) {
                mma_bf16(acc[mf][nf], ah[mf][0], ah[mf][1], ah[mf][2], ah[mf][3], bh0, bh1);
                mma_bf16(acc[mf][nf], ah[mf][0], ah[mf][1], ah[mf][2], ah[mf][3], bl0, bl1);
                mma_bf16(acc[mf][nf], al[mf][0], al[mf][1], al[mf][2], al[mf][3], bh0, bh1);
            }
        }
    }

    #pragma unroll
    for (int mf = 0; mf < 2; mf++) {
        #pragma unroll
        for (int rr = 0; rr < 2; rr++) {
            int m = m0 + mrow + mf * 16 + grp + rr * 8;
            int bidx = m >> 10, s = m & 1023;
            size_t rowbase = ((size_t)bidx * Hh) * Sx;
            #pragma unroll
            for (int nf = 0; nf < 8; nf++) {
                int n = n0 + ncol + nf * 8 + qd * 2;
                int h = n >> 6, d = n & 63;
                float2 o;
                o.x = acc[mf][nf][rr * 2 + 0] + bias[n];
                o.y = acc[mf][nf][rr * 2 + 1] + bias[n + 1];
                *reinterpret_cast<float2*>(
                    &dst[((rowbase + (size_t)h * Sx + s)) * Dd + d]) = o;
            }
        }
    }
}

// ---------------------------------------------------------------------------
// Fused attention — EXACT round-2 kernel (measured 1751 us). Do not touch.
// ---------------------------------------------------------------------------
#define PQ  68
#define PK  66
#define PKS 68
#define PT  130
#define PP  66

#define ATT_SMEM_FLOATS (64 * (PQ + PK + PKS + PT + PP))
#define ATT_SMEM_BYTES  (ATT_SMEM_FLOATS * 4)

__global__ __launch_bounds__(256, 2) void attn_kernel(
    const float* __restrict__ dist, float* __restrict__ out)
{
    extern __shared__ float sm[];
    float* q_t = sm;
    float* k_t = q_t + 64 * PQ;
    float* k_s = k_t + 64 * PK;
    float* T_t = k_s + 64 * PKS;
    float* p_s = T_t + 64 * PT;

    const int tid = threadIdx.x;
    const int tx = tid & 15, ty = tid >> 4;
    const int bh = blockIdx.y;
    const int b = bh >> 4, h = bh & 15;
    const int l0 = blockIdx.x * 64;

    const float* qg = g_q + (size_t)bh * Sx * Dd;
    const float* kg = g_k + (size_t)bh * Sx * Dd;

    for (int idx = tid; idx < 64 * 16; idx += 256) {
        int l = idx >> 4, d4 = (idx & 15) * 4;
        float4 v = *reinterpret_cast<const float4*>(qg + (size_t)(l0 + l) * 64 + d4);
        q_t[(d4 + 0) * PQ + l] = v.x;
        q_t[(d4 + 1) * PQ + l] = v.y;
        q_t[(d4 + 2) * PQ + l] = v.z;
        q_t[(d4 + 3) * PQ + l] = v.w;
    }

    float mrow[4], lrow[4];
    u64 o_p[4][2];
    #pragma unroll
    for (int ii = 0; ii < 4; ii++) {
        mrow[ii] = -CUDART_INF_F;
        lrow[ii] = 0.f;
        o_p[ii][0] = 0ULL;
        o_p[ii][1] = 0ULL;
    }

    const int base = (ty - tx) * 4 + 63;

    for (int r0 = 0; r0 < Sx; r0 += 64) {
        __syncthreads();
        for (int idx = tid; idx < 64 * 16; idx += 256) {
            int r = idx >> 4, d4 = (idx & 15) * 4;
            float4 v = *reinterpret_cast<const float4*>(kg + (size_t)(r0 + r) * 64 + d4);
            *reinterpret_cast<float4*>(&k_s[r * PKS + d4]) = v;
            k_t[(d4 + 0) * PK + r] = v.x;
            k_t[(d4 + 1) * PK + r] = v.y;
            k_t[(d4 + 2) * PK + r] = v.z;
            k_t[(d4 + 3) * PK + r] = v.w;
        }
        const int off = l0 - r0 + 960;
        for (int idx = tid; idx < 127 * 16; idx += 256) {
            int row = idx >> 4, d4 = (idx & 15) * 4;
            float4 v = *reinterpret_cast<const float4*>(dist + (size_t)(off + row) * 64 + d4);
            T_t[(d4 + 0) * PT + row] = v.x;
            T_t[(d4 + 1) * PT + row] = v.y;
            T_t[(d4 + 2) * PT + row] = v.z;
            T_t[(d4 + 3) * PT + row] = v.w;
        }
        __syncthreads();

        u64 accs_p[4][2], accq_p[4][2], acck_p[2][4];
        #pragma unroll
        for (int i = 0; i < 4; i++) {
            accs_p[i][0] = 0ULL; accs_p[i][1] = 0ULL;
            accq_p[i][0] = 0ULL; accq_p[i][1] = 0ULL;
        }
        #pragma unroll
        for (int i = 0; i < 2; i++)
            #pragma unroll
            for (int j = 0; j < 4; j++) acck_p[i][j] = 0ULL;

        for (int d = 0; d < 64; d++) {
            float4 qv = *reinterpret_cast<float4*>(&q_t[d * PQ + ty * 4]);
            u64 qd[4];
            qd[0] = pk(qv.x, qv.x); qd[1] = pk(qv.y, qv.y);
            qd[2] = pk(qv.z, qv.z); qd[3] = pk(qv.w, qv.w);

            float2 kc0 = *reinterpret_cast<float2*>(&k_t[d * PK + tx * 4]);
            float2 kc1 = *reinterpret_cast<float2*>(&k_t[d * PK + tx * 4 + 2]);
            u64 kp[2];
            kp[0] = pk(kc0.x, kc0.y);
            kp[1] = pk(kc1.x, kc1.y);
            u64 kd[4];
            kd[0] = pk(kc0.x, kc0.x); kd[1] = pk(kc0.y, kc0.y);
            kd[2] = pk(kc1.x, kc1.x); kd[3] = pk(kc1.y, kc1.y);

            const float* Trow = &T_t[d * PT + base - 3];
            float2 e0 = *reinterpret_cast<const float2*>(Trow);
            float2 e1 = *reinterpret_cast<const float2*>(Trow + 2);
            float2 e2 = *reinterpret_cast<const float2*>(Trow + 4);
            float  s3 = Trow[6];
            u64 tp[6];
            tp[0] = pk(e0.x, e0.y);
            tp[1] = pk(e0.y, e1.x);
            tp[2] = pk(e1.x, e1.y);
            tp[3] = pk(e1.y, e2.x);
            tp[4] = pk(e2.x, e2.y);
            tp[5] = pk(e2.y, s3);

            #pragma unroll
            for (int ii = 0; ii < 4; ii++)
                #pragma unroll
                for (int jp = 0; jp < 2; jp++) {
                    fma2(accs_p[ii][jp], qd[ii], kp[jp]);
                    fma2(accq_p[ii][jp], qd[ii], tp[ii - 2 * jp + 2]);
                }
            #pragma unroll
            for (int ip = 0; ip < 2; ip++)
                #pragma unroll
                for (int jj = 0; jj < 4; jj++)
                    fma2(acck_p[ip][jj], kd[jj], tp[2 * ip - jj + 3]);
        }

        float st[4][4];
        #pragma unroll
        for (int ii = 0; ii < 4; ii++)
            #pragma unroll
            for (int jp = 0; jp < 2; jp++) {
                float a0, a1;
                upk(accs_p[ii][jp], a0, a1);
                st[ii][2 * jp] = a0;
                st[ii][2 * jp + 1] = a1;
                upk(accq_p[ii][jp], a0, a1);
                st[ii][2 * jp + 1] += a0;
                st[ii][2 * jp] += a1;
            }
        #pragma unroll
        for (int ip = 0; ip < 2; ip++)
            #pragma unroll
            for (int jj = 0; jj < 4; jj++) {
                float a0, a1;
                upk(acck_p[ip][jj], a0, a1);
                st[2 * ip][jj] += a0;
                st[2 * ip + 1][jj] += a1;
            }

        #pragma unroll
        for (int ii = 0; ii < 4; ii++) {
            float tmax = -CUDART_INF_F;
            #pragma unroll
            for (int jj = 0; jj < 4; jj++) {
                st[ii][jj] *= 0.125f;
                tmax = fmaxf(tmax, st[ii][jj]);
            }
            #pragma unroll
            for (int ofs = 8; ofs >= 1; ofs >>= 1)
                tmax = fmaxf(tmax, __shfl_xor_sync(0xffffffffu, tmax, ofs));
            float mnew = fmaxf(mrow[ii], tmax);
            float corr = __expf(mrow[ii] - mnew);
            mrow[ii] = mnew;
            float psum = 0.f;
            #pragma unroll
            for (int jj = 0; jj < 4; jj++) {
                float p = __expf(st[ii][jj] - mnew);
                st[ii][jj] = p;
                psum += p;
            }
            #pragma unroll
            for (int ofs = 8; ofs >= 1; ofs >>= 1)
                psum += __shfl_xor_sync(0xffffffffu, psum, ofs);
            lrow[ii] = lrow[ii] * corr + psum;
            u64 c2 = pk(corr, corr);
            o_p[ii][0] = mul2(o_p[ii][0], c2);
            o_p[ii][1] = mul2(o_p[ii][1], c2);
        }

        #pragma unroll
        for (int ii = 0; ii < 4; ii++)
            #pragma unroll
            for (int jj = 0; jj < 4; jj++)
                p_s[(ty * 4 + ii) * PP + tx * 4 + jj] = st[ii][jj];
        __syncthreads();

        for (int j = 0; j < 64; j += 2) {
            float4 va4 = *reinterpret_cast<float4*>(&k_s[j * PKS + tx * 4]);
            float4 vb4 = *reinterpret_cast<float4*>(&k_s[(j + 1) * PKS + tx * 4]);
            u64 va0 = pk(va4.x, va4.y), va1 = pk(va4.z, va4.w);
            u64 vb0 = pk(vb4.x, vb4.y), vb1 = pk(vb4.z, vb4.w);
            #pragma unroll
            for (int ii = 0; ii < 4; ii++) {
                float2 p2 = *reinterpret_cast<float2*>(&p_s[(ty * 4 + ii) * PP + j]);
                u64 pa = pk(p2.x, p2.x);
                u64 pb = pk(p2.y, p2.y);
                fma2(o_p[ii][0], pa, va0);
                fma2(o_p[ii][1], pa, va1);
                fma2(o_p[ii][0], pb, vb0);
                fma2(o_p[ii][1], pb, vb1);
            }
        }
    }

    #pragma unroll
    for (int ii = 0; ii < 4; ii++) {
        float inv = 1.0f / lrow[ii];
        int srow = l0 + ty * 4 + ii;
        size_t obase = ((size_t)b * Sx + srow) * HIDD + h * 64 + tx * 4;
        float o0, o1, o2, o3;
        upk(o_p[ii][0], o0, o1);
        upk(o_p[ii][1], o2, o3);
        float4 ov;
        ov.x = o0 * inv; ov.y = o1 * inv; ov.z = o2 * inv; ov.w = o3 * inv;
        *reinterpret_cast<float4*>(&out[obase]) = ov;
    }
}

// ---------------------------------------------------------------------------
extern "C" void kernel_launch(void* const* d_in, const int* in_sizes, int n_in,
                              void* d_out, int out_size)
{
    const float* hidden = (const float*)d_in[0];
    const float* Wq = (const float*)d_in[1];
    const float* bq = (const float*)d_in[2];
    const float* Wk = (const float*)d_in[3];
    const float* bk = (const float*)d_in[4];
    // d_in[5], d_in[6] (Wv, bv) dead: reference uses k-projection as v.
    const float* dist = (const float*)d_in[7];
    float* out = (float*)d_out;

    cudaFuncSetAttribute(attn_kernel,
                         cudaFuncAttributeMaxDynamicSharedMemorySize,
                         ATT_SMEM_BYTES);

    transpose_w<<<dim3(32, 32, 2), 256>>>(Wq, Wk);
    proj_mma_kernel<<<dim3(HIDD / 128, (Bb * Sx) / 128, 2), 256>>>(
        hidden, bq, bk);
    attn_kernel<<<dim3(Sx / 64, Bb * Hh), 256, ATT_SMEM_BYTES>>>(dist, out);
}

// round 14
// speedup vs baseline: 1.0469x; 1.0009x over previous
#include <cuda_runtime.h>
#include <cstdint>
#include <math.h>
#include <math_constants.h>

#define Bb   8
#define Sx   1024
#define Hh   16
#define Dd   64
#define HIDD 1024

__device__ float g_q[Bb * Hh * Sx * Dd];
__device__ float g_k[Bb * Hh * Sx * Dd];
__device__ float g_wt[2][HIDD * HIDD];

typedef unsigned long long u64;

// ---------------------------------------------------------------------------
// Packed fp32x2 helpers (attention kernel)
// ---------------------------------------------------------------------------
__device__ __forceinline__ u64 pk(float lo, float hi) {
    u64 r;
    asm("mov.b64 %0, {%1, %2};"
        : "=l"(r) : "r"(__float_as_uint(lo)), "r"(__float_as_uint(hi)));
    return r;
}
__device__ __forceinline__ void upk(u64 v, float& lo, float& hi) {
    unsigned int a, b;
    asm("mov.b64 {%0, %1}, %2;" : "=r"(a), "=r"(b) : "l"(v));
    lo = __uint_as_float(a);
    hi = __uint_as_float(b);
}
__device__ __forceinline__ void fma2(u64& d, u64 a, u64 b) {
    asm("fma.rn.f32x2 %0, %1, %2, %0;" : "+l"(d) : "l"(a), "l"(b));
}
__device__ __forceinline__ u64 mul2(u64 a, u64 b) {
    u64 r;
    asm("mul.rn.f32x2 %0, %1, %2;" : "=l"(r) : "l"(a), "l"(b));
    return r;
}

// ---------------------------------------------------------------------------
// bf16 helpers (mma.sync m16n8k16 — plain sm_80+ PTX)
// ---------------------------------------------------------------------------
__device__ __forceinline__ uint32_t cvt_bf16x2(float lo, float hi) {
    // result = {hi16: cvt(hi), lo16: cvt(lo)}
    uint32_t r;
    asm("cvt.rn.bf16x2.f32 %0, %1, %2;" : "=r"(r) : "f"(hi), "f"(lo));
    return r;
}
__device__ __forceinline__ void mma_bf16(float c[4],
    uint32_t a0, uint32_t a1, uint32_t a2, uint32_t a3,
    uint32_t b0, uint32_t b1)
{
    asm volatile(
        "mma.sync.aligned.m16n8k16.row.col.f32.bf16.bf16.f32 "
        "{%0,%1,%2,%3}, {%4,%5,%6,%7}, {%8,%9}, {%0,%1,%2,%3};"
        : "+f"(c[0]), "+f"(c[1]), "+f"(c[2]), "+f"(c[3])
        : "r"(a0), "r"(a1), "r"(a2), "r"(a3), "r"(b0), "r"(b1));
}

// ---------------------------------------------------------------------------
// Weight transpose: g_wt[z][n][k] = W[k][n]   (measured ~6 us)
// ---------------------------------------------------------------------------
__global__ __launch_bounds__(256) void transpose_w(
    const float* __restrict__ Wq, const float* __restrict__ Wk)
{
    __shared__ float t[32][33];
    const float* W = (blockIdx.z == 0) ? Wq : Wk;
    float* dst = g_wt[blockIdx.z];
    const int x0 = blockIdx.x * 32, y0 = blockIdx.y * 32;
    const int tx = threadIdx.x & 31, ty = threadIdx.x >> 5;
    #pragma unroll
    for (int r = ty; r < 32; r += 8)
        t[r][tx] = W[(size_t)(y0 + r) * HIDD + x0 + tx];
    __syncthreads();
    #pragma unroll
    for (int r = ty; r < 32; r += 8)
        dst[(size_t)(x0 + r) * HIDD + y0 + tx] = t[tx][r];
}

// ---------------------------------------------------------------------------
// Projection GEMM: mma.sync bf16 m16n8k16, 3-term split
//   D = Ah@Bh + Ah@Bl + Al@Bh,   x = bf16_hi(x) + bf16_lo(x - hi)
// 128x128 tile, 8 warps = 4(m) x 2(n), warp tile 32x64.
// K chunked by 16 (one k16 mma per fragment set). Pair-packed smem, pitch 12.
// ---------------------------------------------------------------------------
#define KC      16
#define PITCHP  12   // pairs per row incl. pad (8 data + 4); 12g+qd distinct mod 32

__global__ __launch_bounds__(256, 2) void proj_mma_kernel(
    const float* __restrict__ X,
    const float* __restrict__ bq, const float* __restrict__ bk)
{
    __shared__ uint32_t Ah[128 * PITCHP], Al[128 * PITCHP];
    __shared__ uint32_t Bh[128 * PITCHP], Bl[128 * PITCHP];

    const int tid = threadIdx.x;
    const int wid = tid >> 5, lane = tid & 31;
    const int grp = lane >> 2, qd = lane & 3;
    const int z = blockIdx.z;
    const int n0 = blockIdx.x * 128, m0 = blockIdx.y * 128;
    const float* Wt = g_wt[z];
    const float* bias = z ? bk : bq;
    float* dst = z ? g_k : g_q;

    const int mrow = (wid & 3) * 32;
    const int ncol = (wid >> 2) * 64;

    float acc[2][8][4];
    #pragma unroll
    for (int mf = 0; mf < 2; mf++)
        #pragma unroll
        for (int nf = 0; nf < 8; nf++)
            #pragma unroll
            for (int r = 0; r < 4; r++) acc[mf][nf][r] = 0.f;

    for (int c = 0; c < HIDD / KC; c++) {
        const int kbase = c * KC;
        __syncthreads();
        // Stage A (hidden) and B (Wt) chunks, split to bf16 hi/lo pair-packed.
        #pragma unroll
        for (int half = 0; half < 2; half++) {
            const float* src = half ? (Wt + (size_t)n0 * HIDD + kbase)
                                    : (X + (size_t)m0 * HIDD + kbase);
            uint32_t* dh = half ? Bh : Ah;
            uint32_t* dl = half ? Bl : Al;
            #pragma unroll
            for (int i = tid; i < 512; i += 256) {
                int row = i >> 2, s = i & 3;  // s: which float4 (4 k = 2 pairs)
                float4 v = *reinterpret_cast<const float4*>(
                    src + (size_t)row * HIDD + s * 4);
                uint32_t h0 = cvt_bf16x2(v.x, v.y);
                float hx = __uint_as_float(h0 << 16);
                float hy = __uint_as_float(h0 & 0xffff0000u);
                uint32_t l0 = cvt_bf16x2(v.x - hx, v.y - hy);
                uint32_t h1 = cvt_bf16x2(v.z, v.w);
                float hz = __uint_as_float(h1 << 16);
                float hw = __uint_as_float(h1 & 0xffff0000u);
                uint32_t l1 = cvt_bf16x2(v.z - hz, v.w - hw);
                int o = row * PITCHP + 2 * s;
                dh[o] = h0; dh[o + 1] = h1;
                dl[o] = l0; dl[o + 1] = l1;
            }
        }
        __syncthreads();

        // Fragments: A pairs [row][qd], [row][qd+4]; B pairs [n][qd], [n][qd+4]
        uint32_t ah[2][4], al[2][4];
        #pragma unroll
        for (int mf = 0; mf < 2; mf++) {
            int r0 = (mrow + mf * 16 + grp) * PITCHP + qd;
            int r1 = (mrow + mf * 16 + grp + 8) * PITCHP + qd;
            ah[mf][0] = Ah[r0];     ah[mf][1] = Ah[r1];
            ah[mf][2] = Ah[r0 + 4]; ah[mf][3] = Ah[r1 + 4];
            al[mf][0] = Al[r0];     al[mf][1] = Al[r1];
            al[mf][2] = Al[r0 + 4]; al[mf][3] = Al[r1 + 4];
        }
        #pragma unroll
        for (int nf = 0; nf < 8; nf++) {
            int bb = (ncol + nf * 8 + grp) * PITCHP + qd;
            uint32_t bh0 = Bh[bb], bh1 = Bh[bb + 4];
            uint32_t bl0 = Bl[bb], bl1 = Bl[bb + 4];
            #pragma unroll
            for (int mf = 0; mf < 2; mf++) {
                mma_bf16(acc[mf][nf], ah[mf][0], ah[mf][1], ah[mf][2], ah[mf][3], bh0, bh1);
                mma_bf16(acc[mf][nf], ah[mf][0], ah[mf][1], ah[mf][2], ah[mf][3], bl0, bl1);
                mma_bf16(acc[mf][nf], al[mf][0], al[mf][1], al[mf][2], al[mf][3], bh0, bh1);
            }
        }
    }

    #pragma unroll
    for (int mf = 0; mf < 2; mf++) {
        #pragma unroll
        for (int rr = 0; rr < 2; rr++) {
            int m = m0 + mrow + mf * 16 + grp + rr * 8;
            int bidx = m >> 10, s = m & 1023;
            size_t rowbase = ((size_t)bidx * Hh) * Sx;
            #pragma unroll
            for (int nf = 0; nf < 8; nf++) {
                int n = n0 + ncol + nf * 8 + qd * 2;
                int h = n >> 6, d = n & 63;
                float2 o;
                o.x = acc[mf][nf][rr * 2 + 0] + bias[n];
                o.y = acc[mf][nf][rr * 2 + 1] + bias[n + 1];
                *reinterpret_cast<float2*>(
                    &dst[((rowbase + (size_t)h * Sx + s)) * Dd + d]) = o;
            }
        }
    }
}

// ---------------------------------------------------------------------------
// Fused attention — EXACT round-2 kernel (measured 1751 us). Do not touch.
// ---------------------------------------------------------------------------
#define PQ  68
#define PK  66
#define PKS 68
#define PT  130
#define PP  66

#define ATT_SMEM_FLOATS (64 * (PQ + PK + PKS + PT + PP))
#define ATT_SMEM_BYTES  (ATT_SMEM_FLOATS * 4)

__global__ __launch_bounds__(256, 2) void attn_kernel(
    const float* __restrict__ dist, float* __restrict__ out)
{
    extern __shared__ float sm[];
    float* q_t = sm;
    float* k_t = q_t + 64 * PQ;
    float* k_s = k_t + 64 * PK;
    float* T_t = k_s + 64 * PKS;
    float* p_s = T_t + 64 * PT;

    const int tid = threadIdx.x;
    const int tx = tid & 15, ty = tid >> 4;
    const int bh = blockIdx.y;
    const int b = bh >> 4, h = bh & 15;
    const int l0 = blockIdx.x * 64;

    const float* qg = g_q + (size_t)bh * Sx * Dd;
    const float* kg = g_k + (size_t)bh * Sx * Dd;

    for (int idx = tid; idx < 64 * 16; idx += 256) {
        int l = idx >> 4, d4 = (idx & 15) * 4;
        float4 v = *reinterpret_cast<const float4*>(qg + (size_t)(l0 + l) * 64 + d4);
        q_t[(d4 + 0) * PQ + l] = v.x;
        q_t[(d4 + 1) * PQ + l] = v.y;
        q_t[(d4 + 2) * PQ + l] = v.z;
        q_t[(d4 + 3) * PQ + l] = v.w;
    }

    float mrow[4], lrow[4];
    u64 o_p[4][2];
    #pragma unroll
    for (int ii = 0; ii < 4; ii++) {
        mrow[ii] = -CUDART_INF_F;
        lrow[ii] = 0.f;
        o_p[ii][0] = 0ULL;
        o_p[ii][1] = 0ULL;
    }

    const int base = (ty - tx) * 4 + 63;

    for (int r0 = 0; r0 < Sx; r0 += 64) {
        __syncthreads();
        for (int idx = tid; idx < 64 * 16; idx += 256) {
            int r = idx >> 4, d4 = (idx & 15) * 4;
            float4 v = *reinterpret_cast<const float4*>(kg + (size_t)(r0 + r) * 64 + d4);
            *reinterpret_cast<float4*>(&k_s[r * PKS + d4]) = v;
            k_t[(d4 + 0) * PK + r] = v.x;
            k_t[(d4 + 1) * PK + r] = v.y;
            k_t[(d4 + 2) * PK + r] = v.z;
            k_t[(d4 + 3) * PK + r] = v.w;
        }
        const int off = l0 - r0 + 960;
        for (int idx = tid; idx < 127 * 16; idx += 256) {
            int row = idx >> 4, d4 = (idx & 15) * 4;
            float4 v = *reinterpret_cast<const float4*>(dist + (size_t)(off + row) * 64 + d4);
            T_t[(d4 + 0) * PT + row] = v.x;
            T_t[(d4 + 1) * PT + row] = v.y;
            T_t[(d4 + 2) * PT + row] = v.z;
            T_t[(d4 + 3) * PT + row] = v.w;
        }
        __syncthreads();

        u64 accs_p[4][2], accq_p[4][2], acck_p[2][4];
        #pragma unroll
        for (int i = 0; i < 4; i++) {
            accs_p[i][0] = 0ULL; accs_p[i][1] = 0ULL;
            accq_p[i][0] = 0ULL; accq_p[i][1] = 0ULL;
        }
        #pragma unroll
        for (int i = 0; i < 2; i++)
            #pragma unroll
            for (int j = 0; j < 4; j++) acck_p[i][j] = 0ULL;

        for (int d = 0; d < 64; d++) {
            float4 qv = *reinterpret_cast<float4*>(&q_t[d * PQ + ty * 4]);
            u64 qd[4];
            qd[0] = pk(qv.x, qv.x); qd[1] = pk(qv.y, qv.y);
            qd[2] = pk(qv.z, qv.z); qd[3] = pk(qv.w, qv.w);

            float2 kc0 = *reinterpret_cast<float2*>(&k_t[d * PK + tx * 4]);
            float2 kc1 = *reinterpret_cast<float2*>(&k_t[d * PK + tx * 4 + 2]);
            u64 kp[2];
            kp[0] = pk(kc0.x, kc0.y);
            kp[1] = pk(kc1.x, kc1.y);
            u64 kd[4];
            kd[0] = pk(kc0.x, kc0.x); kd[1] = pk(kc0.y, kc0.y);
            kd[2] = pk(kc1.x, kc1.x); kd[3] = pk(kc1.y, kc1.y);

            const float* Trow = &T_t[d * PT + base - 3];
            float2 e0 = *reinterpret_cast<const float2*>(Trow);
            float2 e1 = *reinterpret_cast<const float2*>(Trow + 2);
            float2 e2 = *reinterpret_cast<const float2*>(Trow + 4);
            float  s3 = Trow[6];
            u64 tp[6];
            tp[0] = pk(e0.x, e0.y);
            tp[1] = pk(e0.y, e1.x);
            tp[2] = pk(e1.x, e1.y);
            tp[3] = pk(e1.y, e2.x);
            tp[4] = pk(e2.x, e2.y);
            tp[5] = pk(e2.y, s3);

            #pragma unroll
            for (int ii = 0; ii < 4; ii++)
                #pragma unroll
                for (int jp = 0; jp < 2; jp++) {
                    fma2(accs_p[ii][jp], qd[ii], kp[jp]);
                    fma2(accq_p[ii][jp], qd[ii], tp[ii - 2 * jp + 2]);
                }
            #pragma unroll
            for (int ip = 0; ip < 2; ip++)
                #pragma unroll
                for (int jj = 0; jj < 4; jj++)
                    fma2(acck_p[ip][jj], kd[jj], tp[2 * ip - jj + 3]);
        }

        float st[4][4];
        #pragma unroll
        for (int ii = 0; ii < 4; ii++)
            #pragma unroll
            for (int jp = 0; jp < 2; jp++) {
                float a0, a1;
                upk(accs_p[ii][jp], a0, a1);
                st[ii][2 * jp] = a0;
                st[ii][2 * jp + 1] = a1;
                upk(accq_p[ii][jp], a0, a1);
                st[ii][2 * jp + 1] += a0;
                st[ii][2 * jp] += a1;
            }
        #pragma unroll
        for (int ip = 0; ip < 2; ip++)
            #pragma unroll
            for (int jj = 0; jj < 4; jj++) {
                float a0, a1;
                upk(acck_p[ip][jj], a0, a1);
                st[2 * ip][jj] += a0;
                st[2 * ip + 1][jj] += a1;
            }

        #pragma unroll
        for (int ii = 0; ii < 4; ii++) {
            float tmax = -CUDART_INF_F;
            #pragma unroll
            for (int jj = 0; jj < 4; jj++) {
                st[ii][jj] *= 0.125f;
                tmax = fmaxf(tmax, st[ii][jj]);
            }
            #pragma unroll
            for (int ofs = 8; ofs >= 1; ofs >>= 1)
                tmax = fmaxf(tmax, __shfl_xor_sync(0xffffffffu, tmax, ofs));
            float mnew = fmaxf(mrow[ii], tmax);
            float corr = __expf(mrow[ii] - mnew);
            mrow[ii] = mnew;
            float psum = 0.f;
            #pragma unroll
            for (int jj = 0; jj < 4; jj++) {
                float p = __expf(st[ii][jj] - mnew);
                st[ii][jj] = p;
                psum += p;
            }
            #pragma unroll
            for (int ofs = 8; ofs >= 1; ofs >>= 1)
                psum += __shfl_xor_sync(0xffffffffu, psum, ofs);
            lrow[ii] = lrow[ii] * corr + psum;
            u64 c2 = pk(corr, corr);
            o_p[ii][0] = mul2(o_p[ii][0], c2);
            o_p[ii][1] = mul2(o_p[ii][1], c2);
        }

        #pragma unroll
        for (int ii = 0; ii < 4; ii++)
            #pragma unroll
            for (int jj = 0; jj < 4; jj++)
                p_s[(ty * 4 + ii) * PP + tx * 4 + jj] = st[ii][jj];
        __syncthreads();

        for (int j = 0; j < 64; j += 2) {
            float4 va4 = *reinterpret_cast<float4*>(&k_s[j * PKS + tx * 4]);
            float4 vb4 = *reinterpret_cast<float4*>(&k_s[(j + 1) * PKS + tx * 4]);
            u64 va0 = pk(va4.x, va4.y), va1 = pk(va4.z, va4.w);
            u64 vb0 = pk(vb4.x, vb4.y), vb1 = pk(vb4.z, vb4.w);
            #pragma unroll
            for (int ii = 0; ii < 4; ii++) {
                float2 p2 = *reinterpret_cast<float2*>(&p_s[(ty * 4 + ii) * PP + j]);
                u64 pa = pk(p2.x, p2.x);
                u64 pb = pk(p2.y, p2.y);
                fma2(o_p[ii][0], pa, va0);
                fma2(o_p[ii][1], pa, va1);
                fma2(o_p[ii][0], pb, vb0);
                fma2(o_p[ii][1], pb, vb1);
            }
        }
    }

    #pragma unroll
    for (int ii = 0; ii < 4; ii++) {
        float inv = 1.0f / lrow[ii];
        int srow = l0 + ty * 4 + ii;
        size_t obase = ((size_t)b * Sx + srow) * HIDD + h * 64 + tx * 4;
        float o0, o1, o2, o3;
        upk(o_p[ii][0], o0, o1);
        upk(o_p[ii][1], o2, o3);
        float4 ov;
        ov.x = o0 * inv; ov.y = o1 * inv; ov.z = o2 * inv; ov.w = o3 * inv;
        *reinterpret_cast<float4*>(&out[obase]) = ov;
    }
}

// ---------------------------------------------------------------------------
extern "C" void kernel_launch(void* const* d_in, const int* in_sizes, int n_in,
                              void* d_out, int out_size)
{
    const float* hidden = (const float*)d_in[0];
    const float* Wq = (const float*)d_in[1];
    const float* bq = (const float*)d_in[2];
    const float* Wk = (const float*)d_in[3];
    const float* bk = (const float*)d_in[4];
    // d_in[5], d_in[6] (Wv, bv) dead: reference uses k-projection as v.
    const float* dist = (const float*)d_in[7];
    float* out = (float*)d_out;

    cudaFuncSetAttribute(attn_kernel,
                         cudaFuncAttributeMaxDynamicSharedMemorySize,
                         ATT_SMEM_BYTES);

    transpose_w<<<dim3(32, 32, 2), 256>>>(Wq, Wk);
    proj_mma_kernel<<<dim3(HIDD / 128, (Bb * Sx) / 128, 2), 256>>>(
        hidden, bq, bk);
    attn_kernel<<<dim3(Sx / 64, Bb * Hh), 256, ATT_SMEM_BYTES>>>(dist, out);
}

// round 15
// speedup vs baseline: 1.0478x; 1.0009x over previous
#include <cuda_runtime.h>
#include <cstdint>
#include <math.h>
#include <math_constants.h>

#define Bb   8
#define Sx   1024
#define Hh   16
#define Dd   64
#define HIDD 1024

__device__ float g_q[Bb * Hh * Sx * Dd];
__device__ float g_k[Bb * Hh * Sx * Dd];
__device__ float g_wt[2][HIDD * HIDD];

typedef unsigned long long u64;

// ---------------------------------------------------------------------------
// Packed fp32x2 helpers (attention kernel)
// ---------------------------------------------------------------------------
__device__ __forceinline__ u64 pk(float lo, float hi) {
    u64 r;
    asm("mov.b64 %0, {%1, %2};"
        : "=l"(r) : "r"(__float_as_uint(lo)), "r"(__float_as_uint(hi)));
    return r;
}
__device__ __forceinline__ void upk(u64 v, float& lo, float& hi) {
    unsigned int a, b;
    asm("mov.b64 {%0, %1}, %2;" : "=r"(a), "=r"(b) : "l"(v));
    lo = __uint_as_float(a);
    hi = __uint_as_float(b);
}
__device__ __forceinline__ void fma2(u64& d, u64 a, u64 b) {
    asm("fma.rn.f32x2 %0, %1, %2, %0;" : "+l"(d) : "l"(a), "l"(b));
}
__device__ __forceinline__ u64 mul2(u64 a, u64 b) {
    u64 r;
    asm("mul.rn.f32x2 %0, %1, %2;" : "=l"(r) : "l"(a), "l"(b));
    return r;
}

// ---------------------------------------------------------------------------
// bf16 helpers (mma.sync m16n8k16 — plain sm_80+ PTX)
// ---------------------------------------------------------------------------
__device__ __forceinline__ uint32_t cvt_bf16x2(float lo, float hi) {
    // result = {hi16: cvt(hi), lo16: cvt(lo)}
    uint32_t r;
    asm("cvt.rn.bf16x2.f32 %0, %1, %2;" : "=r"(r) : "f"(hi), "f"(lo));
    return r;
}
__device__ __forceinline__ void mma_bf16(float c[4],
    uint32_t a0, uint32_t a1, uint32_t a2, uint32_t a3,
    uint32_t b0, uint32_t b1)
{
    asm volatile(
        "mma.sync.aligned.m16n8k16.row.col.f32.bf16.bf16.f32 "
        "{%0,%1,%2,%3}, {%4,%5,%6,%7}, {%8,%9}, {%0,%1,%2,%3};"
        : "+f"(c[0]), "+f"(c[1]), "+f"(c[2]), "+f"(c[3])
        : "r"(a0), "r"(a1), "r"(a2), "r"(a3), "r"(b0), "r"(b1));
}

// ---------------------------------------------------------------------------
// Weight transpose: g_wt[z][n][k] = W[k][n]   (measured ~6 us)
// ---------------------------------------------------------------------------
__global__ __launch_bounds__(256) void transpose_w(
    const float* __restrict__ Wq, const float* __restrict__ Wk)
{
    __shared__ float t[32][33];
    const float* W = (blockIdx.z == 0) ? Wq : Wk;
    float* dst = g_wt[blockIdx.z];
    const int x0 = blockIdx.x * 32, y0 = blockIdx.y * 32;
    const int tx = threadIdx.x & 31, ty = threadIdx.x >> 5;
    #pragma unroll
    for (int r = ty; r < 32; r += 8)
        t[r][tx] = W[(size_t)(y0 + r) * HIDD + x0 + tx];
    __syncthreads();
    #pragma unroll
    for (int r = ty; r < 32; r += 8)
        dst[(size_t)(x0 + r) * HIDD + y0 + tx] = t[tx][r];
}

// ---------------------------------------------------------------------------
// Projection GEMM: mma.sync bf16 m16n8k16, 3-term split
//   D = Ah@Bh + Ah@Bl + Al@Bh,   x = bf16_hi(x) + bf16_lo(x - hi)
// 128x128 tile, 8 warps = 4(m) x 2(n), warp tile 32x64.
// K chunked by 16 (one k16 mma per fragment set). Pair-packed smem, pitch 12.
// ---------------------------------------------------------------------------
#define KC      16
#define PITCHP  12   // pairs per row incl. pad (8 data + 4); 12g+qd distinct mod 32

__global__ __launch_bounds__(256, 2) void proj_mma_kernel(
    const float* __restrict__ X,
    const float* __restrict__ bq, const float* __restrict__ bk)
{
    __shared__ uint32_t Ah[128 * PITCHP], Al[128 * PITCHP];
    __shared__ uint32_t Bh[128 * PITCHP], Bl[128 * PITCHP];

    const int tid = threadIdx.x;
    const int wid = tid >> 5, lane = tid & 31;
    const int grp = lane >> 2, qd = lane & 3;
    const int z = blockIdx.z;
    const int n0 = blockIdx.x * 128, m0 = blockIdx.y * 128;
    const float* Wt = g_wt[z];
    const float* bias = z ? bk : bq;
    float* dst = z ? g_k : g_q;

    const int mrow = (wid & 3) * 32;
    const int ncol = (wid >> 2) * 64;

    float acc[2][8][4];
    #pragma unroll
    for (int mf = 0; mf < 2; mf++)
        #pragma unroll
        for (int nf = 0; nf < 8; nf++)
            #pragma unroll
            for (int r = 0; r < 4; r++) acc[mf][nf][r] = 0.f;

    for (int c = 0; c < HIDD / KC; c++) {
        const int kbase = c * KC;
        __syncthreads();
        // Stage A (hidden) and B (Wt) chunks, split to bf16 hi/lo pair-packed.
        #pragma unroll
        for (int half = 0; half < 2; half++) {
            const float* src = half ? (Wt + (size_t)n0 * HIDD + kbase)
                                    : (X + (size_t)m0 * HIDD + kbase);
            uint32_t* dh = half ? Bh : Ah;
            uint32_t* dl = half ? Bl : Al;
            #pragma unroll
            for (int i = tid; i < 512; i += 256) {
                int row = i >> 2, s = i & 3;  // s: which float4 (4 k = 2 pairs)
                float4 v = *reinterpret_cast<const float4*>(
                    src + (size_t)row * HIDD + s * 4);
                uint32_t h0 = cvt_bf16x2(v.x, v.y);
                float hx = __uint_as_float(h0 << 16);
                float hy = __uint_as_float(h0 & 0xffff0000u);
                uint32_t l0 = cvt_bf16x2(v.x - hx, v.y - hy);
                uint32_t h1 = cvt_bf16x2(v.z, v.w);
                float hz = __uint_as_float(h1 << 16);
                float hw = __uint_as_float(h1 & 0xffff0000u);
                uint32_t l1 = cvt_bf16x2(v.z - hz, v.w - hw);
                int o = row * PITCHP + 2 * s;
                dh[o] = h0; dh[o + 1] = h1;
                dl[o] = l0; dl[o + 1] = l1;
            }
        }
        __syncthreads();

        // Fragments: A pairs [row][qd], [row][qd+4]; B pairs [n][qd], [n][qd+4]
        uint32_t ah[2][4], al[2][4];
        #pragma unroll
        for (int mf = 0; mf < 2; mf++) {
            int r0 = (mrow + mf * 16 + grp) * PITCHP + qd;
            int r1 = (mrow + mf * 16 + grp + 8) * PITCHP + qd;
            ah[mf][0] = Ah[r0];     ah[mf][1] = Ah[r1];
            ah[mf][2] = Ah[r0 + 4]; ah[mf][3] = Ah[r1 + 4];
            al[mf][0] = Al[r0];     al[mf][1] = Al[r1];
            al[mf][2] = Al[r0 + 4]; al[mf][3] = Al[r1 + 4];
        }
        #pragma unroll
        for (int nf = 0; nf < 8; nf++) {
            int bb = (ncol + nf * 8 + grp) * PITCHP + qd;
            uint32_t bh0 = Bh[bb], bh1 = Bh[bb + 4];
            uint32_t bl0 = Bl[bb], bl1 = Bl[bb + 4];
            #pragma unroll
            for (int mf = 0; mf < 2; mf++) {
                mma_bf16(acc[mf][nf], ah[mf][0], ah[mf][1], ah[mf][2], ah[mf][3], bh0, bh1);
                mma_bf16(acc[mf][nf], ah[mf][0], ah[mf][1], ah[mf][2], ah[mf][3], bl0, bl1);
                mma_bf16(acc[mf][nf], al[mf][0], al[mf][1], al[mf][2], al[mf][3], bh0, bh1);
            }
        }
    }

    #pragma unroll
    for (int mf = 0; mf < 2; mf++) {
        #pragma unroll
        for (int rr = 0; rr < 2; rr++) {
            int m = m0 + mrow + mf * 16 + grp + rr * 8;
            int bidx = m >> 10, s = m & 1023;
            size_t rowbase = ((size_t)bidx * Hh) * Sx;
            #pragma unroll
            for (int nf = 0; nf < 8; nf++) {
                int n = n0 + ncol + nf * 8 + qd * 2;
                int h = n >> 6, d = n & 63;
                float2 o;
                o.x = acc[mf][nf][rr * 2 + 0] + bias[n];
                o.y = acc[mf][nf][rr * 2 + 1] + bias[n + 1];
                *reinterpret_cast<float2*>(
                    &dst[((rowbase + (size_t)h * Sx + s)) * Dd + d]) = o;
            }
        }
    }
}

// ---------------------------------------------------------------------------
// Fused attention — EXACT round-2 kernel (measured 1751 us). Do not touch.
// ---------------------------------------------------------------------------
#define PQ  68
#define PK  66
#define PKS 68
#define PT  130
#define PP  66

#define ATT_SMEM_FLOATS (64 * (PQ + PK + PKS + PT + PP))
#define ATT_SMEM_BYTES  (ATT_SMEM_FLOATS * 4)

__global__ __launch_bounds__(256, 2) void attn_kernel(
    const float* __restrict__ dist, float* __restrict__ out)
{
    extern __shared__ float sm[];
    float* q_t = sm;
    float* k_t = q_t + 64 * PQ;
    float* k_s = k_t + 64 * PK;
    float* T_t = k_s + 64 * PKS;
    float* p_s = T_t + 64 * PT;

    const int tid = threadIdx.x;
    const int tx = tid & 15, ty = tid >> 4;
    const int bh = blockIdx.y;
    const int b = bh >> 4, h = bh & 15;
    const int l0 = blockIdx.x * 64;

    const float* qg = g_q + (size_t)bh * Sx * Dd;
    const float* kg = g_k + (size_t)bh * Sx * Dd;

    for (int idx = tid; idx < 64 * 16; idx += 256) {
        int l = idx >> 4, d4 = (idx & 15) * 4;
        float4 v = *reinterpret_cast<const float4*>(qg + (size_t)(l0 + l) * 64 + d4);
        q_t[(d4 + 0) * PQ + l] = v.x;
        q_t[(d4 + 1) * PQ + l] = v.y;
        q_t[(d4 + 2) * PQ + l] = v.z;
        q_t[(d4 + 3) * PQ + l] = v.w;
    }

    float mrow[4], lrow[4];
    u64 o_p[4][2];
    #pragma unroll
    for (int ii = 0; ii < 4; ii++) {
        mrow[ii] = -CUDART_INF_F;
        lrow[ii] = 0.f;
        o_p[ii][0] = 0ULL;
        o_p[ii][1] = 0ULL;
    }

    const int base = (ty - tx) * 4 + 63;

    for (int r0 = 0; r0 < Sx; r0 += 64) {
        __syncthreads();
        for (int idx = tid; idx < 64 * 16; idx += 256) {
            int r = idx >> 4, d4 = (idx & 15) * 4;
            float4 v = *reinterpret_cast<const float4*>(kg + (size_t)(r0 + r) * 64 + d4);
            *reinterpret_cast<float4*>(&k_s[r * PKS + d4]) = v;
            k_t[(d4 + 0) * PK + r] = v.x;
            k_t[(d4 + 1) * PK + r] = v.y;
            k_t[(d4 + 2) * PK + r] = v.z;
            k_t[(d4 + 3) * PK + r] = v.w;
        }
        const int off = l0 - r0 + 960;
        for (int idx = tid; idx < 127 * 16; idx += 256) {
            int row = idx >> 4, d4 = (idx & 15) * 4;
            float4 v = *reinterpret_cast<const float4*>(dist + (size_t)(off + row) * 64 + d4);
            T_t[(d4 + 0) * PT + row] = v.x;
            T_t[(d4 + 1) * PT + row] = v.y;
            T_t[(d4 + 2) * PT + row] = v.z;
            T_t[(d4 + 3) * PT + row] = v.w;
        }
        __syncthreads();

        u64 accs_p[4][2], accq_p[4][2], acck_p[2][4];
        #pragma unroll
        for (int i = 0; i < 4; i++) {
            accs_p[i][0] = 0ULL; accs_p[i][1] = 0ULL;
            accq_p[i][0] = 0ULL; accq_p[i][1] = 0ULL;
        }
        #pragma unroll
        for (int i = 0; i < 2; i++)
            #pragma unroll
            for (int j = 0; j < 4; j++) acck_p[i][j] = 0ULL;

        for (int d = 0; d < 64; d++) {
            float4 qv = *reinterpret_cast<float4*>(&q_t[d * PQ + ty * 4]);
            u64 qd[4];
            qd[0] = pk(qv.x, qv.x); qd[1] = pk(qv.y, qv.y);
            qd[2] = pk(qv.z, qv.z); qd[3] = pk(qv.w, qv.w);

            float2 kc0 = *reinterpret_cast<float2*>(&k_t[d * PK + tx * 4]);
            float2 kc1 = *reinterpret_cast<float2*>(&k_t[d * PK + tx * 4 + 2]);
            u64 kp[2];
            kp[0] = pk(kc0.x, kc0.y);
            kp[1] = pk(kc1.x, kc1.y);
            u64 kd[4];
            kd[0] = pk(kc0.x, kc0.x); kd[1] = pk(kc0.y, kc0.y);
            kd[2] = pk(kc1.x, kc1.x); kd[3] = pk(kc1.y, kc1.y);

            const float* Trow = &T_t[d * PT + base - 3];
            float2 e0 = *reinterpret_cast<const float2*>(Trow);
            float2 e1 = *reinterpret_cast<const float2*>(Trow + 2);
            float2 e2 = *reinterpret_cast<const float2*>(Trow + 4);
            float  s3 = Trow[6];
            u64 tp[6];
            tp[0] = pk(e0.x, e0.y);
            tp[1] = pk(e0.y, e1.x);
            tp[2] = pk(e1.x, e1.y);
            tp[3] = pk(e1.y, e2.x);
            tp[4] = pk(e2.x, e2.y);
            tp[5] = pk(e2.y, s3);

            #pragma unroll
            for (int ii = 0; ii < 4; ii++)
                #pragma unroll
                for (int jp = 0; jp < 2; jp++) {
                    fma2(accs_p[ii][jp], qd[ii], kp[jp]);
                    fma2(accq_p[ii][jp], qd[ii], tp[ii - 2 * jp + 2]);
                }
            #pragma unroll
            for (int ip = 0; ip < 2; ip++)
                #pragma unroll
                for (int jj = 0; jj < 4; jj++)
                    fma2(acck_p[ip][jj], kd[jj], tp[2 * ip - jj + 3]);
        }

        float st[4][4];
        #pragma unroll
        for (int ii = 0; ii < 4; ii++)
            #pragma unroll
            for (int jp = 0; jp < 2; jp++) {
                float a0, a1;
                upk(accs_p[ii][jp], a0, a1);
                st[ii][2 * jp] = a0;
                st[ii][2 * jp + 1] = a1;
                upk(accq_p[ii][jp], a0, a1);
                st[ii][2 * jp + 1] += a0;
                st[ii][2 * jp] += a1;
            }
        #pragma unroll
        for (int ip = 0; ip < 2; ip++)
            #pragma unroll
            for (int jj = 0; jj < 4; jj++) {
                float a0, a1;
                upk(acck_p[ip][jj], a0, a1);
                st[2 * ip][jj] += a0;
                st[2 * ip + 1][jj] += a1;
            }

        #pragma unroll
        for (int ii = 0; ii < 4; ii++) {
            float tmax = -CUDART_INF_F;
            #pragma unroll
            for (int jj = 0; jj < 4; jj++) {
                st[ii][jj] *= 0.125f;
                tmax = fmaxf(tmax, st[ii][jj]);
            }
            #pragma unroll
            for (int ofs = 8; ofs >= 1; ofs >>= 1)
                tmax = fmaxf(tmax, __shfl_xor_sync(0xffffffffu, tmax, ofs));
            float mnew = fmaxf(mrow[ii], tmax);
            float corr = __expf(mrow[ii] - mnew);
            mrow[ii] = mnew;
            float psum = 0.f;
            #pragma unroll
            for (int jj = 0; jj < 4; jj++) {
                float p = __expf(st[ii][jj] - mnew);
                st[ii][jj] = p;
                psum += p;
            }
            #pragma unroll
            for (int ofs = 8; ofs >= 1; ofs >>= 1)
                psum += __shfl_xor_sync(0xffffffffu, psum, ofs);
            lrow[ii] = lrow[ii] * corr + psum;
            u64 c2 = pk(corr, corr);
            o_p[ii][0] = mul2(o_p[ii][0], c2);
            o_p[ii][1] = mul2(o_p[ii][1], c2);
        }

        #pragma unroll
        for (int ii = 0; ii < 4; ii++)
            #pragma unroll
            for (int jj = 0; jj < 4; jj++)
                p_s[(ty * 4 + ii) * PP + tx * 4 + jj] = st[ii][jj];
        __syncthreads();

        for (int j = 0; j < 64; j += 2) {
            float4 va4 = *reinterpret_cast<float4*>(&k_s[j * PKS + tx * 4]);
            float4 vb4 = *reinterpret_cast<float4*>(&k_s[(j + 1) * PKS + tx * 4]);
            u64 va0 = pk(va4.x, va4.y), va1 = pk(va4.z, va4.w);
            u64 vb0 = pk(vb4.x, vb4.y), vb1 = pk(vb4.z, vb4.w);
            #pragma unroll
            for (int ii = 0; ii < 4; ii++) {
                float2 p2 = *reinterpret_cast<float2*>(&p_s[(ty * 4 + ii) * PP + j]);
                u64 pa = pk(p2.x, p2.x);
                u64 pb = pk(p2.y, p2.y);
                fma2(o_p[ii][0], pa, va0);
                fma2(o_p[ii][1], pa, va1);
                fma2(o_p[ii][0], pb, vb0);
                fma2(o_p[ii][1], pb, vb1);
            }
        }
    }

    #pragma unroll
    for (int ii = 0; ii < 4; ii++) {
        float inv = 1.0f / lrow[ii];
        int srow = l0 + ty * 4 + ii;
        size_t obase = ((size_t)b * Sx + srow) * HIDD + h * 64 + tx * 4;
        float o0, o1, o2, o3;
        upk(o_p[ii][0], o0, o1);
        upk(o_p[ii][1], o2, o3);
        float4 ov;
        ov.x = o0 * inv; ov.y = o1 * inv; ov.z = o2 * inv; ov.w = o3 * inv;
        *reinterpret_cast<float4*>(&out[obase]) = ov;
    }
}

// ---------------------------------------------------------------------------
extern "C" void kernel_launch(void* const* d_in, const int* in_sizes, int n_in,
                              void* d_out, int out_size)
{
    const float* hidden = (const float*)d_in[0];
    const float* Wq = (const float*)d_in[1];
    const float* bq = (const float*)d_in[2];
    const float* Wk = (const float*)d_in[3];
    const float* bk = (const float*)d_in[4];
    // d_in[5], d_in[6] (Wv, bv) dead: reference uses k-projection as v.
    const float* dist = (const float*)d_in[7];
    float* out = (float*)d_out;

    cudaFuncSetAttribute(attn_kernel,
                         cudaFuncAttributeMaxDynamicSharedMemorySize,
                         ATT_SMEM_BYTES);

    transpose_w<<<dim3(32, 32, 2), 256>>>(Wq, Wk);
    proj_mma_kernel<<<dim3(HIDD / 128, (Bb * Sx) / 128, 2), 256>>>(
        hidden, bq, bk);
    attn_kernel<<<dim3(Sx / 64, Bb * Hh), 256, ATT_SMEM_BYTES>>>(dist, out);
}